// round 9
// baseline (speedup 1.0000x reference)
#include <cuda_runtime.h>
#include <cuda_bf16.h>
#include <cstdint>
#include <cstddef>

// Problem constants
#define TT   2048
#define HH   1024
#define EE   1024
#define VV   32000
#define G4   4096
#define NCTA 128
#define UPC  8

// ---------------- scratch (no allocations allowed) ----------------
__device__ float g_xg[(size_t)TT * G4];                       // [T,4H] fp32
__device__ float g_scores[(size_t)TT * VV];                   // [T,V] fp32
__device__ __align__(16) __nv_bfloat16 g_x16[(size_t)TT * EE];
__device__ __align__(16) __nv_bfloat16 g_wih16[(size_t)G4 * EE];
__device__ __align__(16) __nv_bfloat16 g_wout16[(size_t)VV * HH];
__device__ __align__(16) __nv_bfloat16 g_hs16[(size_t)TT * HH];
__device__ float g_hbuf[2][HH];
__device__ __align__(128) unsigned g_flag[NCTA * 8]; // per-CTA flag, 32B apart
__device__ __align__(128) unsigned g_rel;            // combiner's release word

// ---------------- sync primitives ----------------
__device__ __forceinline__ void st_release(unsigned* p, unsigned v) {
    asm volatile("st.release.gpu.global.u32 [%0], %1;" :: "l"(p), "r"(v) : "memory");
}
__device__ __forceinline__ unsigned ld_acquire(const unsigned* p) {
    unsigned v;
    asm volatile("ld.acquire.gpu.global.u32 %0, [%1];" : "=r"(v) : "l"(p) : "memory");
    return v;
}

// ---------------- init + conversions ----------------
__global__ void zero_sync_kernel() {
    int i = threadIdx.x;
    if (i < NCTA * 8) g_flag[i] = 0u;
    if (i == 0) g_rel = 0u;
}

__global__ void gather_x16_kernel(const int* __restrict__ seq,
                                  const float* __restrict__ emb)
{
    int t = blockIdx.x;
    const float4* src = (const float4*)(emb + (size_t)seq[t] * EE);
    uint2* dst = (uint2*)(g_x16 + (size_t)t * EE);
    int i = threadIdx.x;            // 256 threads, EE/4 = 256 float4
    float4 v = src[i];
    __nv_bfloat162 a = __floats2bfloat162_rn(v.x, v.y);
    __nv_bfloat162 b = __floats2bfloat162_rn(v.z, v.w);
    dst[i] = make_uint2(*(unsigned*)&a, *(unsigned*)&b);
}

__global__ void f2bf4_kernel(const float4* __restrict__ src,
                             uint2* __restrict__ dst, size_t n4)
{
    size_t i = (size_t)blockIdx.x * blockDim.x + threadIdx.x;
    size_t stride = (size_t)gridDim.x * blockDim.x;
    for (; i < n4; i += stride) {
        float4 v = src[i];
        __nv_bfloat162 a = __floats2bfloat162_rn(v.x, v.y);
        __nv_bfloat162 b = __floats2bfloat162_rn(v.z, v.w);
        dst[i] = make_uint2(*(unsigned*)&a, *(unsigned*)&b);
    }
}

// =================================================================
// bf16 tensor-core GEMM (identical to the proven round-2 version)
// =================================================================
#define SKP 40

__device__ __forceinline__ void ldsm_x4(uint32_t& r0, uint32_t& r1,
                                        uint32_t& r2, uint32_t& r3,
                                        const __nv_bfloat16* p)
{
    uint32_t addr = (uint32_t)__cvta_generic_to_shared(p);
    asm volatile("ldmatrix.sync.aligned.m8n8.x4.shared.b16 {%0,%1,%2,%3}, [%4];\n"
                 : "=r"(r0), "=r"(r1), "=r"(r2), "=r"(r3) : "r"(addr));
}

__device__ __forceinline__ void mma16816(float* d, const uint32_t* a,
                                         const uint32_t* b)
{
    asm volatile(
        "mma.sync.aligned.m16n8k16.row.col.f32.bf16.bf16.f32 "
        "{%0,%1,%2,%3}, {%4,%5,%6,%7}, {%8,%9}, {%0,%1,%2,%3};\n"
        : "+f"(d[0]), "+f"(d[1]), "+f"(d[2]), "+f"(d[3])
        : "r"(a[0]), "r"(a[1]), "r"(a[2]), "r"(a[3]), "r"(b[0]), "r"(b[1]));
}

__global__ void __launch_bounds__(256) bgemm_tn(
    const __nv_bfloat16* __restrict__ A, const __nv_bfloat16* __restrict__ B,
    const float* __restrict__ bias1, const float* __restrict__ bias2,
    float* __restrict__ C, int M, int N, int K)
{
    __shared__ __nv_bfloat16 Asm[2][128 * SKP];
    __shared__ __nv_bfloat16 Bsm[2][128 * SKP];

    const int tid = threadIdx.x;
    const int lane = tid & 31;
    const int w = tid >> 5;
    const int wm = w >> 2;
    const int wn = w & 3;
    const int bm = blockIdx.y * 128, bn = blockIdx.x * 128;

    const int c0 = tid, c1 = tid + 256;
    const int r0g = c0 >> 2, k0g = (c0 & 3) * 8;
    const int r1g = c1 >> 2, k1g = (c1 & 3) * 8;
    const __nv_bfloat16* Ap0 = A + (size_t)(bm + r0g) * K + k0g;
    const __nv_bfloat16* Ap1 = A + (size_t)(bm + r1g) * K + k1g;
    const __nv_bfloat16* Bp0 = B + (size_t)(bn + r0g) * K + k0g;
    const __nv_bfloat16* Bp1 = B + (size_t)(bn + r1g) * K + k1g;

    float acc[4][4][4];
#pragma unroll
    for (int i = 0; i < 4; ++i)
#pragma unroll
        for (int j = 0; j < 4; ++j)
#pragma unroll
            for (int q = 0; q < 4; ++q) acc[i][j][q] = 0.f;

    {
        float4 a0 = *(const float4*)Ap0;
        float4 a1 = *(const float4*)Ap1;
        float4 b0 = *(const float4*)Bp0;
        float4 b1 = *(const float4*)Bp1;
        *(float4*)&Asm[0][r0g * SKP + k0g] = a0;
        *(float4*)&Asm[0][r1g * SKP + k1g] = a1;
        *(float4*)&Bsm[0][r0g * SKP + k0g] = b0;
        *(float4*)&Bsm[0][r1g * SKP + k1g] = b1;
    }
    __syncthreads();

    const int KT = K / 32;
    for (int kt = 0; kt < KT; ++kt) {
        const int cur = kt & 1, nxt = cur ^ 1;
        float4 pa0, pa1, pb0, pb1;
        if (kt + 1 < KT) {
            int ko = (kt + 1) * 32;
            pa0 = *(const float4*)(Ap0 + ko);
            pa1 = *(const float4*)(Ap1 + ko);
            pb0 = *(const float4*)(Bp0 + ko);
            pb1 = *(const float4*)(Bp1 + ko);
        }

        const __nv_bfloat16* As = Asm[cur];
        const __nv_bfloat16* Bs = Bsm[cur];
#pragma unroll
        for (int ks = 0; ks < 2; ++ks) {
            uint32_t af[4][4];
#pragma unroll
            for (int mf = 0; mf < 4; ++mf)
                ldsm_x4(af[mf][0], af[mf][1], af[mf][2], af[mf][3],
                        &As[(wm * 64 + mf * 16 + (lane & 15)) * SKP
                            + ks * 16 + (lane >> 4) * 8]);
            uint32_t bf[4][2];
#pragma unroll
            for (int p = 0; p < 2; ++p) {
                uint32_t r0, r1, r2, r3;
                ldsm_x4(r0, r1, r2, r3,
                        &Bs[(wn * 32 + p * 16 + ((lane >> 4) << 3) + (lane & 7)) * SKP
                            + ks * 16 + ((lane >> 3) & 1) * 8]);
                bf[p * 2][0] = r0; bf[p * 2][1] = r1;
                bf[p * 2 + 1][0] = r2; bf[p * 2 + 1][1] = r3;
            }
#pragma unroll
            for (int mf = 0; mf < 4; ++mf)
#pragma unroll
                for (int nf = 0; nf < 4; ++nf)
                    mma16816(acc[mf][nf], af[mf], bf[nf]);
        }

        if (kt + 1 < KT) {
            *(float4*)&Asm[nxt][r0g * SKP + k0g] = pa0;
            *(float4*)&Asm[nxt][r1g * SKP + k1g] = pa1;
            *(float4*)&Bsm[nxt][r0g * SKP + k0g] = pb0;
            *(float4*)&Bsm[nxt][r1g * SKP + k1g] = pb1;
            __syncthreads();
        }
    }

    const int gid = lane >> 2, tg = lane & 3;
#pragma unroll
    for (int mf = 0; mf < 4; ++mf) {
        int row0 = bm + wm * 64 + mf * 16 + gid;
#pragma unroll
        for (int nf = 0; nf < 4; ++nf) {
            int col = bn + wn * 32 + nf * 8 + tg * 2;
            float b0 = 0.f, b1 = 0.f;
            if (bias1) { b0 += bias1[col]; b1 += bias1[col + 1]; }
            if (bias2) { b0 += bias2[col]; b1 += bias2[col + 1]; }
            C[(size_t)row0 * N + col]           = acc[mf][nf][0] + b0;
            C[(size_t)row0 * N + col + 1]       = acc[mf][nf][1] + b1;
            C[(size_t)(row0 + 8) * N + col]     = acc[mf][nf][2] + b0;
            C[(size_t)(row0 + 8) * N + col + 1] = acc[mf][nf][3] + b1;
        }
    }
}

// =================================================================
// Persistent LSTM scan — single-combiner flag barrier.
//   arrive: tid0 st.release to its OWN flag (128 distinct 32B sectors,
//           zero serialization)
//   combine: ONE warp on the chip (CTA0 warp0) ld.acquire-sweeps the
//           128 flags (~0.4 loads/cyc) and st.release's g_rel = t
//   wait:   ONE thread per CTA polls g_rel (127 pollers — the fan-in
//           that measured fastest across R2/R5/R7), then __syncthreads
//           propagates the acquire CTA-wide.
// Poll sits at the TOP of the iteration. No atomics, no threadfence.
// Flags zeroed per launch (graph-replay safe).
// =================================================================
__global__ void __launch_bounds__(256, 1) lstm_scan_kernel(
    const float* __restrict__ h0, const float* __restrict__ c0,
    const float* __restrict__ W_hh, float* __restrict__ out_tail)
{
    __shared__ float sh[HH];
    const int tid  = threadIdx.x;
    const int lane = tid & 31;
    const int w    = tid >> 5;
    const int j    = blockIdx.x * UPC + w;

    float4 wreg[4][8];
#pragma unroll
    for (int g = 0; g < 4; ++g)
#pragma unroll
        for (int i = 0; i < 8; ++i)
            wreg[g][i] = *(const float4*)(W_hh + (size_t)(g * HH + j) * HH
                                          + lane * 4 + 128 * i);

    float c_reg = c0[j];

    for (int t = 0; t < TT; ++t) {
        // ---- barrier wait (for step t-1's h) ----
        if (t > 0) {
            if (blockIdx.x == 0) {
                if (w == 0) {               // the chip's only combiner warp
                    const unsigned tgt = (unsigned)t;
                    bool ok;
                    do {
                        ok = true;
#pragma unroll
                        for (int i = 0; i < 4; ++i) {
                            unsigned f = ld_acquire(&g_flag[(i * 32 + lane) * 8]);
                            ok &= ((int)(f - tgt) >= 0);
                        }
                    } while (!__all_sync(0xffffffffu, ok));
                    if (lane == 0) st_release(&g_rel, tgt);
                }
            } else {
                if (tid == 0) {             // one poller per CTA
                    while ((int)(ld_acquire(&g_rel) - (unsigned)t) < 0) { }
                }
            }
            __syncthreads();                // propagate acquire CTA-wide
        }

        const float* hsrc = (t == 0) ? h0 : g_hbuf[t & 1];
        float4 hv = __ldcg((const float4*)hsrc + tid);
        float xgv = 0.f;
        if (lane < 4)
            xgv = __ldcg(&g_xg[(size_t)t * G4 + lane * HH + j]);
        *((float4*)sh + tid) = hv;
        __syncthreads();

        float4 hreg[8];
#pragma unroll
        for (int i = 0; i < 8; ++i)
            hreg[i] = *((const float4*)sh + lane + 32 * i);

        float gate[4];
#pragma unroll
        for (int g = 0; g < 4; ++g) {
            float s0 = 0.f, s1 = 0.f;        // 2 accumulators: halve FFMA chain
#pragma unroll
            for (int i = 0; i < 4; ++i) {
                s0 += wreg[g][i].x * hreg[i].x + wreg[g][i].y * hreg[i].y
                    + wreg[g][i].z * hreg[i].z + wreg[g][i].w * hreg[i].w;
                s1 += wreg[g][i + 4].x * hreg[i + 4].x + wreg[g][i + 4].y * hreg[i + 4].y
                    + wreg[g][i + 4].z * hreg[i + 4].z + wreg[g][i + 4].w * hreg[i + 4].w;
            }
            float s = s0 + s1;
#pragma unroll
            for (int o = 16; o; o >>= 1) s += __shfl_xor_sync(0xffffffffu, s, o);
            gate[g] = s;                     // every lane holds the sum
        }

        // lanes 0-3 each evaluate one activation
        float a = 0.f;
        if (lane < 4) {
            float pre = xgv + (lane == 0 ? gate[0] : lane == 1 ? gate[1]
                               : lane == 2 ? gate[2] : gate[3]);
            if (lane == 2) {
                a = 1.f - __fdividef(2.f, __expf(2.f * pre) + 1.f);  // tanh
            } else {
                a = __fdividef(1.f, 1.f + __expf(-pre));             // sigmoid
            }
        }
        float i_ = __shfl_sync(0xffffffffu, a, 0);
        float f_ = __shfl_sync(0xffffffffu, a, 1);
        float g_ = __shfl_sync(0xffffffffu, a, 2);
        float o_ = __shfl_sync(0xffffffffu, a, 3);

        float h_ = 0.f;
        if (lane == 0) {
            c_reg = f_ * c_reg + i_ * g_;
            float tc = 1.f - __fdividef(2.f, __expf(2.f * c_reg) + 1.f);
            h_ = o_ * tc;
            g_hbuf[(t + 1) & 1][j] = h_;     // critical-path store only
        }

        if (t < TT - 1) {
            __syncthreads();                 // CTA's 8 h-stores done (CTA hb)
            if (tid == 0)
                st_release(&g_flag[blockIdx.x * 8], (unsigned)(t + 1));
            if (lane == 0)                   // off-critical-path bookkeeping
                g_hs16[(size_t)t * HH + j] = __float2bfloat16(h_);
        } else {
            if (lane == 0) {
                g_hs16[(size_t)t * HH + j] = __float2bfloat16(h_);
                out_tail[j] = h_; out_tail[HH + j] = c_reg;
            }
        }
    }
}

// =================================================================
// Row log-softmax
// =================================================================
__global__ void __launch_bounds__(256) logsoftmax_kernel(
    const float* __restrict__ scores, float* __restrict__ out)
{
    __shared__ float red[256];
    const int row = blockIdx.x;
    const int tid = threadIdx.x;
    const float* s = scores + (size_t)row * VV;

    float mx = -3.402823466e38f;
    for (int v = tid; v < VV; v += 256) mx = fmaxf(mx, s[v]);
    red[tid] = mx; __syncthreads();
    for (int st = 128; st > 0; st >>= 1) {
        if (tid < st) red[tid] = fmaxf(red[tid], red[tid + st]);
        __syncthreads();
    }
    mx = red[0]; __syncthreads();

    float sum = 0.f;
    for (int v = tid; v < VV; v += 256) sum += __expf(s[v] - mx);
    red[tid] = sum; __syncthreads();
    for (int st = 128; st > 0; st >>= 1) {
        if (tid < st) red[tid] += red[tid + st];
        __syncthreads();
    }
    float L = mx + logf(red[0]);

    float* o = out + (size_t)row * VV;
    for (int v = tid; v < VV; v += 256) o[v] = s[v] - L;
}

// =================================================================
extern "C" void kernel_launch(void* const* d_in, const int* in_sizes, int n_in,
                              void* d_out, int out_size)
{
    (void)in_sizes; (void)n_in; (void)out_size;
    const int*   seq   = (const int*)  d_in[0];
    const float* h0    = (const float*)d_in[1];
    const float* c0    = (const float*)d_in[2];
    const float* emb   = (const float*)d_in[3];
    const float* W_ih  = (const float*)d_in[4];
    const float* W_hh  = (const float*)d_in[5];
    const float* b_ih  = (const float*)d_in[6];
    const float* b_hh  = (const float*)d_in[7];
    const float* W_out = (const float*)d_in[8];
    const float* b_out = (const float*)d_in[9];
    float* out = (float*)d_out;

    float *p_xg = nullptr, *p_scores = nullptr;
    __nv_bfloat16 *p_x16 = nullptr, *p_wih16 = nullptr, *p_wout16 = nullptr,
                  *p_hs16 = nullptr;
    cudaGetSymbolAddress((void**)&p_xg, g_xg);
    cudaGetSymbolAddress((void**)&p_scores, g_scores);
    cudaGetSymbolAddress((void**)&p_x16, g_x16);
    cudaGetSymbolAddress((void**)&p_wih16, g_wih16);
    cudaGetSymbolAddress((void**)&p_wout16, g_wout16);
    cudaGetSymbolAddress((void**)&p_hs16, g_hs16);

    // 0) reset barrier state (stream-serialized before the scan)
    zero_sync_kernel<<<1, 1024>>>();

    // conversions (vectorized)
    gather_x16_kernel<<<TT, 256>>>(seq, emb);
    f2bf4_kernel<<<512, 256>>>((const float4*)W_ih, (uint2*)p_wih16,
                               (size_t)G4 * EE / 4);
    f2bf4_kernel<<<2048, 256>>>((const float4*)W_out, (uint2*)p_wout16,
                                (size_t)VV * HH / 4);

    // 1) xg = x @ W_ih^T + (b_ih + b_hh)   [T, 4H]
    {
        dim3 grid(G4 / 128, TT / 128);
        bgemm_tn<<<grid, 256>>>(p_x16, p_wih16, b_ih, b_hh, p_xg, TT, G4, EE);
    }
    // 2) sequential LSTM scan
    lstm_scan_kernel<<<NCTA, 256>>>(h0, c0, W_hh, out + (size_t)TT * VV);
    // 3) scores = hs @ W_out^T + b_out     [T, V]
    {
        dim3 grid(VV / 128, TT / 128);
        bgemm_tn<<<grid, 256>>>(p_hs16, p_wout16, b_out, nullptr, p_scores,
                                TT, VV, HH);
    }
    // 4) logp = log_softmax(scores) -> d_out
    logsoftmax_kernel<<<TT, 256>>>(p_scores, out);
}

// round 10
// speedup vs baseline: 1.8677x; 1.8677x over previous
#include <cuda_runtime.h>
#include <cuda_bf16.h>
#include <cstdint>
#include <cstddef>

// Problem constants
#define TT   2048
#define HH   1024
#define EE   1024
#define VV   32000
#define G4   4096
#define NCTA 128
#define UPC  8

// ---------------- scratch (no allocations allowed) ----------------
__device__ float g_xg[(size_t)TT * G4];                       // [T,4H] fp32
__device__ float g_scores[(size_t)TT * VV];                   // [T,V] fp32
__device__ __align__(16) __nv_bfloat16 g_x16[(size_t)TT * EE];
__device__ __align__(16) __nv_bfloat16 g_wih16[(size_t)G4 * EE];
__device__ __align__(16) __nv_bfloat16 g_wout16[(size_t)VV * HH];
__device__ __align__(16) __nv_bfloat16 g_hs16[(size_t)TT * HH];
__device__ float g_hbuf[2][HH];
__device__ unsigned g_arrive;    // monotonic counters (R2-proven, replay-safe)
__device__ unsigned g_release;

// ---------------- conversions ----------------
__global__ void gather_x16_kernel(const int* __restrict__ seq,
                                  const float* __restrict__ emb)
{
    int t = blockIdx.x;
    const float4* src = (const float4*)(emb + (size_t)seq[t] * EE);
    uint2* dst = (uint2*)(g_x16 + (size_t)t * EE);
    int i = threadIdx.x;            // 256 threads, EE/4 = 256 float4
    float4 v = src[i];
    __nv_bfloat162 a = __floats2bfloat162_rn(v.x, v.y);
    __nv_bfloat162 b = __floats2bfloat162_rn(v.z, v.w);
    dst[i] = make_uint2(*(unsigned*)&a, *(unsigned*)&b);
}

__global__ void f2bf4_kernel(const float4* __restrict__ src,
                             uint2* __restrict__ dst, size_t n4)
{
    size_t i = (size_t)blockIdx.x * blockDim.x + threadIdx.x;
    size_t stride = (size_t)gridDim.x * blockDim.x;
    for (; i < n4; i += stride) {
        float4 v = src[i];
        __nv_bfloat162 a = __floats2bfloat162_rn(v.x, v.y);
        __nv_bfloat162 b = __floats2bfloat162_rn(v.z, v.w);
        dst[i] = make_uint2(*(unsigned*)&a, *(unsigned*)&b);
    }
}

// =================================================================
// bf16 tensor-core GEMM (identical to the proven round-2 version)
// =================================================================
#define SKP 40

__device__ __forceinline__ void ldsm_x4(uint32_t& r0, uint32_t& r1,
                                        uint32_t& r2, uint32_t& r3,
                                        const __nv_bfloat16* p)
{
    uint32_t addr = (uint32_t)__cvta_generic_to_shared(p);
    asm volatile("ldmatrix.sync.aligned.m8n8.x4.shared.b16 {%0,%1,%2,%3}, [%4];\n"
                 : "=r"(r0), "=r"(r1), "=r"(r2), "=r"(r3) : "r"(addr));
}

__device__ __forceinline__ void mma16816(float* d, const uint32_t* a,
                                         const uint32_t* b)
{
    asm volatile(
        "mma.sync.aligned.m16n8k16.row.col.f32.bf16.bf16.f32 "
        "{%0,%1,%2,%3}, {%4,%5,%6,%7}, {%8,%9}, {%0,%1,%2,%3};\n"
        : "+f"(d[0]), "+f"(d[1]), "+f"(d[2]), "+f"(d[3])
        : "r"(a[0]), "r"(a[1]), "r"(a[2]), "r"(a[3]), "r"(b[0]), "r"(b[1]));
}

__global__ void __launch_bounds__(256) bgemm_tn(
    const __nv_bfloat16* __restrict__ A, const __nv_bfloat16* __restrict__ B,
    const float* __restrict__ bias1, const float* __restrict__ bias2,
    float* __restrict__ C, int M, int N, int K)
{
    __shared__ __nv_bfloat16 Asm[2][128 * SKP];
    __shared__ __nv_bfloat16 Bsm[2][128 * SKP];

    const int tid = threadIdx.x;
    const int lane = tid & 31;
    const int w = tid >> 5;
    const int wm = w >> 2;
    const int wn = w & 3;
    const int bm = blockIdx.y * 128, bn = blockIdx.x * 128;

    const int c0 = tid, c1 = tid + 256;
    const int r0g = c0 >> 2, k0g = (c0 & 3) * 8;
    const int r1g = c1 >> 2, k1g = (c1 & 3) * 8;
    const __nv_bfloat16* Ap0 = A + (size_t)(bm + r0g) * K + k0g;
    const __nv_bfloat16* Ap1 = A + (size_t)(bm + r1g) * K + k1g;
    const __nv_bfloat16* Bp0 = B + (size_t)(bn + r0g) * K + k0g;
    const __nv_bfloat16* Bp1 = B + (size_t)(bn + r1g) * K + k1g;

    float acc[4][4][4];
#pragma unroll
    for (int i = 0; i < 4; ++i)
#pragma unroll
        for (int j = 0; j < 4; ++j)
#pragma unroll
            for (int q = 0; q < 4; ++q) acc[i][j][q] = 0.f;

    {
        float4 a0 = *(const float4*)Ap0;
        float4 a1 = *(const float4*)Ap1;
        float4 b0 = *(const float4*)Bp0;
        float4 b1 = *(const float4*)Bp1;
        *(float4*)&Asm[0][r0g * SKP + k0g] = a0;
        *(float4*)&Asm[0][r1g * SKP + k1g] = a1;
        *(float4*)&Bsm[0][r0g * SKP + k0g] = b0;
        *(float4*)&Bsm[0][r1g * SKP + k1g] = b1;
    }
    __syncthreads();

    const int KT = K / 32;
    for (int kt = 0; kt < KT; ++kt) {
        const int cur = kt & 1, nxt = cur ^ 1;
        float4 pa0, pa1, pb0, pb1;
        if (kt + 1 < KT) {
            int ko = (kt + 1) * 32;
            pa0 = *(const float4*)(Ap0 + ko);
            pa1 = *(const float4*)(Ap1 + ko);
            pb0 = *(const float4*)(Bp0 + ko);
            pb1 = *(const float4*)(Bp1 + ko);
        }

        const __nv_bfloat16* As = Asm[cur];
        const __nv_bfloat16* Bs = Bsm[cur];
#pragma unroll
        for (int ks = 0; ks < 2; ++ks) {
            uint32_t af[4][4];
#pragma unroll
            for (int mf = 0; mf < 4; ++mf)
                ldsm_x4(af[mf][0], af[mf][1], af[mf][2], af[mf][3],
                        &As[(wm * 64 + mf * 16 + (lane & 15)) * SKP
                            + ks * 16 + (lane >> 4) * 8]);
            uint32_t bf[4][2];
#pragma unroll
            for (int p = 0; p < 2; ++p) {
                uint32_t r0, r1, r2, r3;
                ldsm_x4(r0, r1, r2, r3,
                        &Bs[(wn * 32 + p * 16 + ((lane >> 4) << 3) + (lane & 7)) * SKP
                            + ks * 16 + ((lane >> 3) & 1) * 8]);
                bf[p * 2][0] = r0; bf[p * 2][1] = r1;
                bf[p * 2 + 1][0] = r2; bf[p * 2 + 1][1] = r3;
            }
#pragma unroll
            for (int mf = 0; mf < 4; ++mf)
#pragma unroll
                for (int nf = 0; nf < 4; ++nf)
                    mma16816(acc[mf][nf], af[mf], bf[nf]);
        }

        if (kt + 1 < KT) {
            *(float4*)&Asm[nxt][r0g * SKP + k0g] = pa0;
            *(float4*)&Asm[nxt][r1g * SKP + k1g] = pa1;
            *(float4*)&Bsm[nxt][r0g * SKP + k0g] = pb0;
            *(float4*)&Bsm[nxt][r1g * SKP + k1g] = pb1;
            __syncthreads();
        }
    }

    const int gid = lane >> 2, tg = lane & 3;
#pragma unroll
    for (int mf = 0; mf < 4; ++mf) {
        int row0 = bm + wm * 64 + mf * 16 + gid;
#pragma unroll
        for (int nf = 0; nf < 4; ++nf) {
            int col = bn + wn * 32 + nf * 8 + tg * 2;
            float b0 = 0.f, b1 = 0.f;
            if (bias1) { b0 += bias1[col]; b1 += bias1[col + 1]; }
            if (bias2) { b0 += bias2[col]; b1 += bias2[col + 1]; }
            C[(size_t)row0 * N + col]           = acc[mf][nf][0] + b0;
            C[(size_t)row0 * N + col + 1]       = acc[mf][nf][1] + b1;
            C[(size_t)(row0 + 8) * N + col]     = acc[mf][nf][2] + b0;
            C[(size_t)(row0 + 8) * N + col + 1] = acc[mf][nf][3] + b1;
        }
    }
}

// =================================================================
// Persistent LSTM scan.
// Barrier: EXACT round-2 topology (measured fastest of 5 variants):
//   tid0: atomicAdd(g_arrive); the 128th arriver atomicAdd(g_release);
//   all other tid0's poll the release word (volatile ld). Monotonic
//   counters + relbase read at launch -> graph-replay safe.
// On top of it: parallel activations (lanes 0-3), xg prefetch,
// 2-accumulator dots, hs16 bookkeeping store on lane 1 (never delays
// tid0's barrier work).
// =================================================================
__global__ void __launch_bounds__(256, 1) lstm_scan_kernel(
    const float* __restrict__ h0, const float* __restrict__ c0,
    const float* __restrict__ W_hh, float* __restrict__ out_tail)
{
    __shared__ float sh[HH];
    const int tid  = threadIdx.x;
    const int lane = tid & 31;
    const int w    = tid >> 5;
    const int j    = blockIdx.x * UPC + w;

    float4 wreg[4][8];
#pragma unroll
    for (int g = 0; g < 4; ++g)
#pragma unroll
        for (int i = 0; i < 8; ++i)
            wreg[g][i] = *(const float4*)(W_hh + (size_t)(g * HH + j) * HH
                                          + lane * 4 + 128 * i);

    float c_reg = c0[j];
    const unsigned relbase = *(volatile unsigned*)&g_release; // before 1st arrive

    for (int t = 0; t < TT; ++t) {
        const float* hsrc = (t == 0) ? h0 : g_hbuf[t & 1];
        float4 hv = __ldcg((const float4*)hsrc + tid);
        float xgv = 0.f;
        if (lane < 4)
            xgv = __ldcg(&g_xg[(size_t)t * G4 + lane * HH + j]);
        *((float4*)sh + tid) = hv;
        __syncthreads();

        float4 hreg[8];
#pragma unroll
        for (int i = 0; i < 8; ++i)
            hreg[i] = *((const float4*)sh + lane + 32 * i);

        float gate[4];
#pragma unroll
        for (int g = 0; g < 4; ++g) {
            float s0 = 0.f, s1 = 0.f;        // 2 accumulators: halve FFMA chain
#pragma unroll
            for (int i = 0; i < 4; ++i) {
                s0 += wreg[g][i].x * hreg[i].x + wreg[g][i].y * hreg[i].y
                    + wreg[g][i].z * hreg[i].z + wreg[g][i].w * hreg[i].w;
                s1 += wreg[g][i + 4].x * hreg[i + 4].x + wreg[g][i + 4].y * hreg[i + 4].y
                    + wreg[g][i + 4].z * hreg[i + 4].z + wreg[g][i + 4].w * hreg[i + 4].w;
            }
            float s = s0 + s1;
#pragma unroll
            for (int o = 16; o; o >>= 1) s += __shfl_xor_sync(0xffffffffu, s, o);
            gate[g] = s;                     // every lane holds the sum
        }

        // lanes 0-3 each evaluate one activation
        float a = 0.f;
        if (lane < 4) {
            float pre = xgv + (lane == 0 ? gate[0] : lane == 1 ? gate[1]
                               : lane == 2 ? gate[2] : gate[3]);
            if (lane == 2) {
                a = 1.f - __fdividef(2.f, __expf(2.f * pre) + 1.f);  // tanh
            } else {
                a = __fdividef(1.f, 1.f + __expf(-pre));             // sigmoid
            }
        }
        float i_ = __shfl_sync(0xffffffffu, a, 0);
        float f_ = __shfl_sync(0xffffffffu, a, 1);
        float g_ = __shfl_sync(0xffffffffu, a, 2);
        float o_ = __shfl_sync(0xffffffffu, a, 3);

        float h_ = 0.f;
        if (lane == 0) {
            c_reg = f_ * c_reg + i_ * g_;
            float tc = 1.f - __fdividef(2.f, __expf(2.f * c_reg) + 1.f);
            h_ = o_ * tc;
            g_hbuf[(t + 1) & 1][j] = h_;     // critical-path store
        }
        float h_b = __shfl_sync(0xffffffffu, h_, 0);

        if (t < TT - 1) {
            __threadfence();                 // publish h writes (R2-proven)
            __syncthreads();                 // whole CTA done with step t
            if (lane == 1)                   // bookkeeping off tid0's path
                g_hs16[(size_t)t * HH + j] = __float2bfloat16(h_b);
            if (tid == 0) {
                unsigned target = relbase + (unsigned)t + 1u;
                unsigned aold = atomicAdd(&g_arrive, 1u);
                if ((aold + 1u) % (unsigned)NCTA == 0u) {
                    atomicAdd(&g_release, 1u);   // last arriver releases all
                } else {
                    while ((int)(*(volatile unsigned*)&g_release - target) < 0) { }
                }
            }
            __syncthreads();
        } else {
            if (lane == 1)
                g_hs16[(size_t)t * HH + j] = __float2bfloat16(h_b);
            if (lane == 0) { out_tail[j] = h_; out_tail[HH + j] = c_reg; }
        }
    }
}

// =================================================================
// Row log-softmax — online max/sum in ONE read pass, then write pass.
// =================================================================
__global__ void __launch_bounds__(256) logsoftmax_kernel(
    const float* __restrict__ scores, float* __restrict__ out)
{
    __shared__ float mred[256];
    __shared__ float sred[256];
    const int row = blockIdx.x;
    const int tid = threadIdx.x;
    const float* s = scores + (size_t)row * VV;

    float m = -3.402823466e38f, su = 0.f;
    for (int v = tid; v < VV; v += 256) {
        float x = s[v];
        if (x > m) { su *= __expf(m - x); m = x; }
        su += __expf(x - m);
    }
    mred[tid] = m; sred[tid] = su; __syncthreads();
    for (int st = 128; st > 0; st >>= 1) {
        if (tid < st) {
            float m2 = mred[tid + st], s2 = sred[tid + st];
            float m1 = mred[tid],      s1 = sred[tid];
            float mn = fmaxf(m1, m2);
            sred[tid] = s1 * __expf(m1 - mn) + s2 * __expf(m2 - mn);
            mred[tid] = mn;
        }
        __syncthreads();
    }
    const float L = mred[0] + logf(sred[0]);

    float* o = out + (size_t)row * VV;
    for (int v = tid; v < VV; v += 256) o[v] = s[v] - L;
}

// =================================================================
extern "C" void kernel_launch(void* const* d_in, const int* in_sizes, int n_in,
                              void* d_out, int out_size)
{
    (void)in_sizes; (void)n_in; (void)out_size;
    const int*   seq   = (const int*)  d_in[0];
    const float* h0    = (const float*)d_in[1];
    const float* c0    = (const float*)d_in[2];
    const float* emb   = (const float*)d_in[3];
    const float* W_ih  = (const float*)d_in[4];
    const float* W_hh  = (const float*)d_in[5];
    const float* b_ih  = (const float*)d_in[6];
    const float* b_hh  = (const float*)d_in[7];
    const float* W_out = (const float*)d_in[8];
    const float* b_out = (const float*)d_in[9];
    float* out = (float*)d_out;

    float *p_xg = nullptr, *p_scores = nullptr;
    __nv_bfloat16 *p_x16 = nullptr, *p_wih16 = nullptr, *p_wout16 = nullptr,
                  *p_hs16 = nullptr;
    cudaGetSymbolAddress((void**)&p_xg, g_xg);
    cudaGetSymbolAddress((void**)&p_scores, g_scores);
    cudaGetSymbolAddress((void**)&p_x16, g_x16);
    cudaGetSymbolAddress((void**)&p_wih16, g_wih16);
    cudaGetSymbolAddress((void**)&p_wout16, g_wout16);
    cudaGetSymbolAddress((void**)&p_hs16, g_hs16);

    // conversions (vectorized)
    gather_x16_kernel<<<TT, 256>>>(seq, emb);
    f2bf4_kernel<<<512, 256>>>((const float4*)W_ih, (uint2*)p_wih16,
                               (size_t)G4 * EE / 4);
    f2bf4_kernel<<<2048, 256>>>((const float4*)W_out, (uint2*)p_wout16,
                                (size_t)VV * HH / 4);

    // 1) xg = x @ W_ih^T + (b_ih + b_hh)   [T, 4H]
    {
        dim3 grid(G4 / 128, TT / 128);
        bgemm_tn<<<grid, 256>>>(p_x16, p_wih16, b_ih, b_hh, p_xg, TT, G4, EE);
    }
    // 2) sequential LSTM scan
    lstm_scan_kernel<<<NCTA, 256>>>(h0, c0, W_hh, out + (size_t)TT * VV);
    // 3) scores = hs @ W_out^T + b_out     [T, V]
    {
        dim3 grid(VV / 128, TT / 128);
        bgemm_tn<<<grid, 256>>>(p_hs16, p_wout16, b_out, nullptr, p_scores,
                                TT, VV, HH);
    }
    // 4) logp = log_softmax(scores) -> d_out
    logsoftmax_kernel<<<TT, 256>>>(p_scores, out);
}